// round 1
// baseline (speedup 1.0000x reference)
#include <cuda_runtime.h>
#include <math.h>

#define NN 50000
#define NE 500000
#define DD 128
#define NB_SCALE 98  // ceil(50000/512)

// ---------------- device scratch (static, no runtime alloc) ----------------
__device__ int   g_deg[NN];
__device__ int   g_pos[NN];
__device__ int   g_ptr[NN + 1];
__device__ int   g_eid[NE];
__device__ float g_scale[NN];
__device__ float g_partial[128];
__device__ float g_factor;
__device__ float g_feats[(size_t)NN * 512];   // [N][4][128] mean,max,min,std
__device__ float g_xa[(size_t)NN * DD];
__device__ float g_xb[(size_t)NN * DD];

// ---------------- CSR build ----------------
__global__ void k_zero() {
    int i = blockIdx.x * blockDim.x + threadIdx.x;
    if (i < NN) { g_deg[i] = 0; g_pos[i] = 0; }
}

__global__ void k_hist(const int* __restrict__ ed) {
    int e = blockIdx.x * blockDim.x + threadIdx.x;
    if (e < NE) atomicAdd(&g_deg[ed[e]], 1);
}

__global__ void k_scan() {  // 1 block, 1024 threads: exclusive scan of g_deg -> g_ptr
    __shared__ int sh[1024];
    __shared__ int carry;
    int t = threadIdx.x;
    if (t == 0) carry = 0;
    __syncthreads();
    for (int base = 0; base < NN; base += 1024) {
        int i = base + t;
        int v = (i < NN) ? g_deg[i] : 0;
        sh[t] = v;
        __syncthreads();
        for (int off = 1; off < 1024; off <<= 1) {
            int u = (t >= off) ? sh[t - off] : 0;
            __syncthreads();
            sh[t] += u;
            __syncthreads();
        }
        if (i < NN) g_ptr[i] = carry + sh[t] - v;
        __syncthreads();
        if (t == 0) carry += sh[1023];
        __syncthreads();
    }
    if (t == 0) g_ptr[NN] = carry;
}

__global__ void k_fill(const int* __restrict__ ed) {
    int e = blockIdx.x * blockDim.x + threadIdx.x;
    if (e < NE) {
        int d = ed[e];
        int p = atomicAdd(&g_pos[d], 1);
        g_eid[g_ptr[d] + p] = e;
    }
}

// ---------------- degree scalers ----------------
__global__ void k_scale_partial() {
    __shared__ float sh[512];
    int t = threadIdx.x;
    int i = blockIdx.x * 512 + t;
    float v = (i < NN) ? logf((float)g_deg[i] + 1.0f) : 0.0f;
    sh[t] = v;
    __syncthreads();
    for (int off = 256; off > 0; off >>= 1) {
        if (t < off) sh[t] += sh[t + off];
        __syncthreads();
    }
    if (t == 0) g_partial[blockIdx.x] = sh[0];
}

__global__ void k_scale_final(int nb) {
    __shared__ float sh[128];
    int t = threadIdx.x;
    sh[t] = (t < nb) ? g_partial[t] : 0.0f;
    __syncthreads();
    for (int off = 64; off > 0; off >>= 1) {
        if (t < off) sh[t] += sh[t + off];
        __syncthreads();
    }
    if (t == 0) g_factor = (float)NN / sh[0];
}

__global__ void k_scale_write() {
    int i = blockIdx.x * blockDim.x + threadIdx.x;
    if (i < NN) g_scale[i] = logf((float)g_deg[i] + 1.0f) * g_factor;
}

// ---------------- per-layer aggregation: warp per node, no atomics ----------------
__global__ void k_aggregate(const float* __restrict__ x, const float* __restrict__ x0,
                            const float* __restrict__ relw,
                            const int* __restrict__ es, const int* __restrict__ et,
                            const float* __restrict__ ew) {
    int gw = (blockIdx.x * blockDim.x + threadIdx.x) >> 5;
    int lane = threadIdx.x & 31;
    if (gw >= NN) return;
    int n = gw;
    float4 b = ((const float4*)(x0 + (size_t)n * DD))[lane];
    float4 sum = b, mx = b, mn = b;
    float4 ssq = make_float4(b.x * b.x, b.y * b.y, b.z * b.z, b.w * b.w);
    int p0 = g_ptr[n], p1 = g_ptr[n + 1];
    for (int p = p0; p < p1; ++p) {
        int e = g_eid[p];
        int s = es[e];
        int r = et[e];
        float w = ew[e];
        float4 xv = ((const float4*)(x + (size_t)s * DD))[lane];
        float4 rv = ((const float4*)(relw + (size_t)r * DD))[lane];
        float4 m = make_float4(xv.x * rv.x * w, xv.y * rv.y * w, xv.z * rv.z * w, xv.w * rv.w * w);
        sum.x += m.x; sum.y += m.y; sum.z += m.z; sum.w += m.w;
        ssq.x += m.x * m.x; ssq.y += m.y * m.y; ssq.z += m.z * m.z; ssq.w += m.w * m.w;
        mx.x = fmaxf(mx.x, m.x); mx.y = fmaxf(mx.y, m.y); mx.z = fmaxf(mx.z, m.z); mx.w = fmaxf(mx.w, m.w);
        mn.x = fminf(mn.x, m.x); mn.y = fminf(mn.y, m.y); mn.z = fminf(mn.z, m.z); mn.w = fminf(mn.w, m.w);
    }
    float invd = 1.0f / (float)(p1 - p0 + 1);
    float4 mean = make_float4(sum.x * invd, sum.y * invd, sum.z * invd, sum.w * invd);
    float4 sq = make_float4(ssq.x * invd, ssq.y * invd, ssq.z * invd, ssq.w * invd);
    float4 sd;
    sd.x = sqrtf(fmaxf(sq.x - mean.x * mean.x, 1e-6f));
    sd.y = sqrtf(fmaxf(sq.y - mean.y * mean.y, 1e-6f));
    sd.z = sqrtf(fmaxf(sq.z - mean.z * mean.z, 1e-6f));
    sd.w = sqrtf(fmaxf(sq.w - mean.w * mean.w, 1e-6f));
    float4* out = (float4*)(g_feats + (size_t)n * 512);
    out[0 * 32 + lane] = mean;
    out[1 * 32 + lane] = mx;
    out[2 * 32 + lane] = mn;
    out[3 * 32 + lane] = sd;
}

// ---------------- fused linear + LayerNorm + ReLU + residual ----------------
// out[n,:] = relu(LN(cat(scaled feats, x) @ W + b)) + x[n,:]
// A tile generated on the fly from feats (512 vals/row) and per-node scalers.
// BM=64, BN=128, BK=64, 256 threads, each thread 4x8 accumulators.
__global__ void __launch_bounds__(256) k_linear(
    const float* __restrict__ feats, const float* __restrict__ xin,
    const float* __restrict__ W, const float* __restrict__ bias,
    const float* __restrict__ gam, const float* __restrict__ bet,
    float* __restrict__ xout) {
    extern __shared__ float sm[];
    float* As = sm;           // [64][64] transposed: As[k*64+m]
    float* Bs = sm + 4096;    // [64][132] padded

    int t = threadIdx.x;
    int m0 = blockIdx.x * 64;

    int am = t >> 2;          // A-load row this thread owns
    int akq = t & 3;
    int anode = min(m0 + am, NN - 1);
    float s1 = g_scale[anode];
    float s2 = 1.0f / fmaxf(s1, 1e-2f);

    int ty = t >> 4, tx = t & 15;
    float acc[4][8];
#pragma unroll
    for (int i = 0; i < 4; i++)
#pragma unroll
        for (int j = 0; j < 8; j++) acc[i][j] = 0.0f;

    for (int kt = 0; kt < 26; ++kt) {
        int c0 = kt * 64;
        const float* srcrow;
        float smul;
        if (c0 < 1536) {
            int j = c0 >> 9;            // scaler index 0..2
            int f = (c0 >> 7) & 3;      // feat index 0..3
            int koff = c0 & 127;        // 0 or 64
            smul = (j == 0) ? 1.0f : ((j == 1) ? s1 : s2);
            srcrow = feats + (size_t)anode * 512 + f * 128 + koff;
        } else {
            smul = 1.0f;
            srcrow = xin + (size_t)anode * 128 + (c0 - 1536);
        }
#pragma unroll
        for (int i = 0; i < 4; i++) {
            int k = akq * 16 + i * 4;
            float4 v = *(const float4*)(srcrow + k);
            As[(k + 0) * 64 + am] = v.x * smul;
            As[(k + 1) * 64 + am] = v.y * smul;
            As[(k + 2) * 64 + am] = v.z * smul;
            As[(k + 3) * 64 + am] = v.w * smul;
        }
#pragma unroll
        for (int i = 0; i < 8; i++) {
            int f4 = t + 256 * i;
            int r = f4 >> 5, c4 = f4 & 31;
            float4 v = *(const float4*)(W + (size_t)(c0 + r) * 128 + c4 * 4);
            *(float4*)(Bs + r * 132 + c4 * 4) = v;
        }
        __syncthreads();
#pragma unroll 8
        for (int kk = 0; kk < 64; ++kk) {
            float4 av = *(const float4*)(As + kk * 64 + ty * 4);
            float4 b0 = *(const float4*)(Bs + kk * 132 + tx * 8);
            float4 b1 = *(const float4*)(Bs + kk * 132 + tx * 8 + 4);
            float bb[8] = {b0.x, b0.y, b0.z, b0.w, b1.x, b1.y, b1.z, b1.w};
#pragma unroll
            for (int j = 0; j < 8; j++) {
                acc[0][j] += av.x * bb[j];
                acc[1][j] += av.y * bb[j];
                acc[2][j] += av.z * bb[j];
                acc[3][j] += av.w * bb[j];
            }
        }
        __syncthreads();
    }

    // stage C to smem (overlay As/Bs), then LN per row (warp per row)
    float* Cs = sm;  // [64][132]
#pragma unroll
    for (int i = 0; i < 4; i++) {
        *(float4*)(Cs + (ty * 4 + i) * 132 + tx * 8) =
            make_float4(acc[i][0], acc[i][1], acc[i][2], acc[i][3]);
        *(float4*)(Cs + (ty * 4 + i) * 132 + tx * 8 + 4) =
            make_float4(acc[i][4], acc[i][5], acc[i][6], acc[i][7]);
    }
    __syncthreads();

    int wid = t >> 5, lane = t & 31;
    float4 b4 = *(const float4*)(bias + lane * 4);
    float4 g4 = *(const float4*)(gam + lane * 4);
    float4 be4 = *(const float4*)(bet + lane * 4);
    for (int r = wid; r < 64; r += 8) {
        int node = m0 + r;
        if (node >= NN) break;
        float4 v = *(const float4*)(Cs + r * 132 + lane * 4);
        v.x += b4.x; v.y += b4.y; v.z += b4.z; v.w += b4.w;
        float s = v.x + v.y + v.z + v.w;
        float q = v.x * v.x + v.y * v.y + v.z * v.z + v.w * v.w;
#pragma unroll
        for (int off = 16; off > 0; off >>= 1) {
            s += __shfl_xor_sync(0xffffffffu, s, off);
            q += __shfl_xor_sync(0xffffffffu, q, off);
        }
        float mu = s * (1.0f / 128.0f);
        float var = q * (1.0f / 128.0f) - mu * mu;
        float rs = rsqrtf(var + 1e-5f);
        float4 xr = *(const float4*)(xin + (size_t)node * 128 + lane * 4);
        float4 o;
        o.x = fmaxf((v.x - mu) * rs * g4.x + be4.x, 0.0f) + xr.x;
        o.y = fmaxf((v.y - mu) * rs * g4.y + be4.y, 0.0f) + xr.y;
        o.z = fmaxf((v.z - mu) * rs * g4.z + be4.z, 0.0f) + xr.z;
        o.w = fmaxf((v.w - mu) * rs * g4.w + be4.w, 0.0f) + xr.w;
        *(float4*)(xout + (size_t)node * 128 + lane * 4) = o;
    }
}

// ---------------- DistMult scoring ----------------
__global__ void k_score(const float* __restrict__ x, const float* __restrict__ qw,
                        const int* __restrict__ src, const int* __restrict__ rel,
                        const int* __restrict__ dst, float* __restrict__ out) {
    int i = (blockIdx.x * blockDim.x + threadIdx.x) >> 5;
    int lane = threadIdx.x & 31;
    if (i >= 32768) return;
    int s = src[i], r = rel[i], d = dst[i];
    float4 a = ((const float4*)(x + (size_t)s * DD))[lane];
    float4 q = ((const float4*)(qw + (size_t)r * DD))[lane];
    float4 b = ((const float4*)(x + (size_t)d * DD))[lane];
    float p = a.x * q.x * b.x + a.y * q.y * b.y + a.z * q.z * b.z + a.w * q.w * b.w;
#pragma unroll
    for (int off = 16; off > 0; off >>= 1) p += __shfl_xor_sync(0xffffffffu, p, off);
    if (lane == 0) out[i] = p;
}

// ---------------- launch ----------------
extern "C" void kernel_launch(void* const* d_in, const int* in_sizes, int n_in,
                              void* d_out, int out_size) {
    const float* x0   = (const float*)d_in[0];
    const int*   ei   = (const int*)d_in[1];
    const int*   etyp = (const int*)d_in[2];
    const float* ew   = (const float*)d_in[3];
    const float* relw = (const float*)d_in[4];
    const float* linw = (const float*)d_in[5];
    const float* linb = (const float*)d_in[6];
    const float* lng  = (const float*)d_in[7];
    const float* lnb  = (const float*)d_in[8];
    const float* qw   = (const float*)d_in[9];
    const int*   src  = (const int*)d_in[10];
    const int*   rel  = (const int*)d_in[11];
    const int*   dst  = (const int*)d_in[12];
    float* out = (float*)d_out;
    const int* es = ei;
    const int* ed = ei + NE;

    cudaFuncSetAttribute(k_linear, cudaFuncAttributeMaxDynamicSharedMemorySize, 50176);

    void *pa, *pb, *pf;
    cudaGetSymbolAddress(&pa, g_xa);
    cudaGetSymbolAddress(&pb, g_xb);
    cudaGetSymbolAddress(&pf, g_feats);
    float* XA = (float*)pa;
    float* XB = (float*)pb;
    float* F  = (float*)pf;

    k_zero<<<196, 256>>>();
    k_hist<<<1954, 256>>>(ed);
    k_scan<<<1, 1024>>>();
    k_fill<<<1954, 256>>>(ed);
    k_scale_partial<<<NB_SCALE, 512>>>();
    k_scale_final<<<1, 128>>>(NB_SCALE);
    k_scale_write<<<196, 256>>>();

    const float* xi = x0;
    float* xo = XA;
    for (int l = 0; l < 4; l++) {
        k_aggregate<<<6250, 256>>>(xi, x0, relw + (size_t)l * 51 * 128, es, etyp, ew);
        k_linear<<<782, 256, 50176>>>(F, xi, linw + (size_t)l * 1664 * 128,
                                      linb + l * 128, lng + l * 128, lnb + l * 128, xo);
        xi = xo;
        xo = (xo == XA) ? XB : XA;
    }
    k_score<<<4096, 256>>>(xi, qw, src, rel, dst, out);
}

// round 3
// speedup vs baseline: 2.3703x; 2.3703x over previous
#include <cuda_runtime.h>
#include <cuda_bf16.h>
#include <math.h>
#include <stdint.h>

#define NN 50000
#define NE 500000
#define DD 128
#define NB_SCALE 98
#define NCHUNK 26

// ---------------- device scratch ----------------
__device__ int   g_deg[NN];
__device__ int   g_pos[NN];
__device__ int   g_ptr[NN + 1];
__device__ int   g_eid[NE];
__device__ float g_scale[NN];
__device__ float g_partial[128];
__device__ float g_factor;
__device__ float g_feats[(size_t)NN * 512];
__device__ float g_xa[(size_t)NN * DD];
__device__ float g_xb[(size_t)NN * DD];
// transposed bf16 weight tiles: [4 layers][26 chunks][128 n][64 k]
__device__ __nv_bfloat16 g_Bhi[4 * NCHUNK * 8192];
__device__ __nv_bfloat16 g_Blo[4 * NCHUNK * 8192];

__device__ __forceinline__ uint32_t smem_u32(const void* p) {
    uint32_t a;
    asm("{ .reg .u64 t; cvta.to.shared.u64 t, %1; cvt.u32.u64 %0, t; }" : "=r"(a) : "l"(p));
    return a;
}
__device__ __forceinline__ void ldm_x4(uint32_t addr, uint32_t* r) {
    asm volatile("ldmatrix.sync.aligned.m8n8.x4.shared.b16 {%0,%1,%2,%3}, [%4];"
                 : "=r"(r[0]), "=r"(r[1]), "=r"(r[2]), "=r"(r[3]) : "r"(addr));
}
__device__ __forceinline__ void mma16816(float* c, const uint32_t* a, uint32_t b0, uint32_t b1) {
    asm volatile(
        "mma.sync.aligned.m16n8k16.row.col.f32.bf16.bf16.f32 "
        "{%0,%1,%2,%3}, {%4,%5,%6,%7}, {%8,%9}, {%0,%1,%2,%3};"
        : "+f"(c[0]), "+f"(c[1]), "+f"(c[2]), "+f"(c[3])
        : "r"(a[0]), "r"(a[1]), "r"(a[2]), "r"(a[3]), "r"(b0), "r"(b1));
}

// ---------------- CSR build ----------------
__global__ void k_zero() {
    int i = blockIdx.x * blockDim.x + threadIdx.x;
    if (i < NN) { g_deg[i] = 0; g_pos[i] = 0; }
}
__global__ void k_hist(const int* __restrict__ ed) {
    int e = blockIdx.x * blockDim.x + threadIdx.x;
    if (e < NE) atomicAdd(&g_deg[ed[e]], 1);
}
__global__ void k_scan() {
    __shared__ int sh[1024];
    __shared__ int carry;
    int t = threadIdx.x;
    if (t == 0) carry = 0;
    __syncthreads();
    for (int base = 0; base < NN; base += 1024) {
        int i = base + t;
        int v = (i < NN) ? g_deg[i] : 0;
        sh[t] = v;
        __syncthreads();
        for (int off = 1; off < 1024; off <<= 1) {
            int u = (t >= off) ? sh[t - off] : 0;
            __syncthreads();
            sh[t] += u;
            __syncthreads();
        }
        if (i < NN) g_ptr[i] = carry + sh[t] - v;
        __syncthreads();
        if (t == 0) carry += sh[1023];
        __syncthreads();
    }
    if (t == 0) g_ptr[NN] = carry;
}
__global__ void k_fill(const int* __restrict__ ed) {
    int e = blockIdx.x * blockDim.x + threadIdx.x;
    if (e < NE) {
        int d = ed[e];
        int p = atomicAdd(&g_pos[d], 1);
        g_eid[g_ptr[d] + p] = e;
    }
}
__global__ void k_scale_partial() {
    __shared__ float sh[512];
    int t = threadIdx.x;
    int i = blockIdx.x * 512 + t;
    float v = (i < NN) ? logf((float)g_deg[i] + 1.0f) : 0.0f;
    sh[t] = v;
    __syncthreads();
    for (int off = 256; off > 0; off >>= 1) {
        if (t < off) sh[t] += sh[t + off];
        __syncthreads();
    }
    if (t == 0) g_partial[blockIdx.x] = sh[0];
}
__global__ void k_scale_final(int nb) {
    __shared__ float sh[128];
    int t = threadIdx.x;
    sh[t] = (t < nb) ? g_partial[t] : 0.0f;
    __syncthreads();
    for (int off = 64; off > 0; off >>= 1) {
        if (t < off) sh[t] += sh[t + off];
        __syncthreads();
    }
    if (t == 0) g_factor = (float)NN / sh[0];
}
__global__ void k_scale_write() {
    int i = blockIdx.x * blockDim.x + threadIdx.x;
    if (i < NN) g_scale[i] = logf((float)g_deg[i] + 1.0f) * g_factor;
}

// ---------------- weight prep: transpose + bf16 split (row-major [n][k]) ----------------
__global__ void k_prepw(const float* __restrict__ linw) {
    int idx = blockIdx.x * blockDim.x + threadIdx.x;
    if (idx >= 4 * NCHUNK * 8192) return;
    int tile = idx >> 13;
    int within = idx & 8191;
    int n = within >> 6, kk = within & 63;
    int l = tile / NCHUNK, kt = tile - l * NCHUNK;
    int k = kt * 64 + kk;
    float w = linw[((size_t)l * 1664 + k) * 128 + n];
    __nv_bfloat16 h = __float2bfloat16(w);
    __nv_bfloat16 lo = __float2bfloat16(w - __bfloat162float(h));
    g_Bhi[(size_t)tile * 8192 + within] = h;
    g_Blo[(size_t)tile * 8192 + within] = lo;
}

// ---------------- per-layer aggregation ----------------
__global__ void k_aggregate(const float* __restrict__ x, const float* __restrict__ x0,
                            const float* __restrict__ relw,
                            const int* __restrict__ es, const int* __restrict__ et,
                            const float* __restrict__ ew) {
    int gw = (blockIdx.x * blockDim.x + threadIdx.x) >> 5;
    int lane = threadIdx.x & 31;
    if (gw >= NN) return;
    int n = gw;
    float4 b = ((const float4*)(x0 + (size_t)n * DD))[lane];
    float4 sum = b, mx = b, mn = b;
    float4 ssq = make_float4(b.x * b.x, b.y * b.y, b.z * b.z, b.w * b.w);
    int p0 = g_ptr[n], p1 = g_ptr[n + 1];
    for (int p = p0; p < p1; ++p) {
        int e = g_eid[p];
        int s = es[e];
        int r = et[e];
        float w = ew[e];
        float4 xv = ((const float4*)(x + (size_t)s * DD))[lane];
        float4 rv = ((const float4*)(relw + (size_t)r * DD))[lane];
        float4 m = make_float4(xv.x * rv.x * w, xv.y * rv.y * w, xv.z * rv.z * w, xv.w * rv.w * w);
        sum.x += m.x; sum.y += m.y; sum.z += m.z; sum.w += m.w;
        ssq.x += m.x * m.x; ssq.y += m.y * m.y; ssq.z += m.z * m.z; ssq.w += m.w * m.w;
        mx.x = fmaxf(mx.x, m.x); mx.y = fmaxf(mx.y, m.y); mx.z = fmaxf(mx.z, m.z); mx.w = fmaxf(mx.w, m.w);
        mn.x = fminf(mn.x, m.x); mn.y = fminf(mn.y, m.y); mn.z = fminf(mn.z, m.z); mn.w = fminf(mn.w, m.w);
    }
    float invd = 1.0f / (float)(p1 - p0 + 1);
    float4 mean = make_float4(sum.x * invd, sum.y * invd, sum.z * invd, sum.w * invd);
    float4 sq = make_float4(ssq.x * invd, ssq.y * invd, ssq.z * invd, ssq.w * invd);
    float4 sd;
    sd.x = sqrtf(fmaxf(sq.x - mean.x * mean.x, 1e-6f));
    sd.y = sqrtf(fmaxf(sq.y - mean.y * mean.y, 1e-6f));
    sd.z = sqrtf(fmaxf(sq.z - mean.z * mean.z, 1e-6f));
    sd.w = sqrtf(fmaxf(sq.w - mean.w * mean.w, 1e-6f));
    float4* out = (float4*)(g_feats + (size_t)n * 512);
    out[0 * 32 + lane] = mean;
    out[1 * 32 + lane] = mx;
    out[2 * 32 + lane] = mn;
    out[3 * 32 + lane] = sd;
}

// ---------------- mma.sync fused linear + LN + ReLU + residual ----------------
// CTA 128x128, warp grid 4(M)x2(N), warp tile 32x64.
// SMEM: header 4096B (s1,s2,bias,gam,bet); AH@4096 AL@22528 BH@40960 BL@59392, each [128][72] bf16.
#define SM_AH 4096
#define SM_AL 22528
#define SM_BH 40960
#define SM_BL 59392
#define LIN_SMEM 77824
#define ROWB 144  // bytes per padded row (72 bf16)

__global__ void __launch_bounds__(256) k_linear_mma(
    const float* __restrict__ feats, const float* __restrict__ xin,
    const __nv_bfloat16* __restrict__ Bh, const __nv_bfloat16* __restrict__ Bl,
    const float* __restrict__ bias, const float* __restrict__ gam,
    const float* __restrict__ bet, float* __restrict__ xout) {
    extern __shared__ char smem[];
    uint32_t sb = smem_u32(smem);
    float* shf = (float*)smem;
    int t = threadIdx.x, wid = t >> 5, lane = t & 31;
    int m0 = blockIdx.x * 128;
    int wm = wid >> 1, wn = wid & 1;   // warp tile: rows wm*32, cols wn*64

    if (t < 128) {
        int node = min(m0 + t, NN - 1);
        float s1 = g_scale[node];
        shf[t] = s1;
        shf[128 + t] = 1.0f / fmaxf(s1, 1e-2f);
        shf[256 + t] = bias[t];
        shf[384 + t] = gam[t];
        shf[512 + t] = bet[t];
    }
    __syncthreads();

    float acc[2][8][4];
#pragma unroll
    for (int i = 0; i < 2; i++)
#pragma unroll
        for (int j = 0; j < 8; j++)
#pragma unroll
            for (int q = 0; q < 4; q++) acc[i][j][q] = 0.0f;

    // ldmatrix lane addressing (bytes, relative to tile base)
    int aidx = lane & 7, agrp = lane >> 3;
    int a_row = aidx + ((agrp & 1) ? 8 : 0);
    int a_kof = (agrp & 2) ? 8 : 0;
    int b_row = aidx + ((agrp & 2) ? 8 : 0);
    int b_kof = (agrp & 1) ? 8 : 0;

    for (int kt = 0; kt < NCHUNK; ++kt) {
        int c0 = kt * 64;
        // ---- B copy ----
        {
            const float4* bsh = (const float4*)(Bh + (size_t)kt * 8192);
            const float4* bsl = (const float4*)(Bl + (size_t)kt * 8192);
#pragma unroll
            for (int q = 0; q < 4; ++q) {
                int i = t + q * 256;
                int n = i >> 3, c = i & 7;
                *(float4*)(smem + SM_BH + n * ROWB + c * 16) = bsh[i];
                *(float4*)(smem + SM_BL + n * ROWB + c * 16) = bsl[i];
            }
        }
        // ---- A generate ----
        {
            int j = c0 >> 9, f = (c0 >> 7) & 3, koff = c0 & 127;
            bool isx = (c0 >= 1536);
#pragma unroll
            for (int it = 0; it < 16; ++it) {
                int e2 = t + it * 256;
                int m = e2 >> 5;
                int kk = (e2 & 31) * 2;
                int node = m0 + m;
                if (node > NN - 1) node = NN - 1;
                float smul;
                const float* sr;
                if (isx) {
                    smul = 1.0f;
                    sr = xin + (size_t)node * 128 + (c0 - 1536);
                } else {
                    smul = (j == 0) ? 1.0f : ((j == 1) ? shf[m] : shf[128 + m]);
                    sr = feats + (size_t)node * 512 + f * 128 + koff;
                }
                float2 v = *(const float2*)(sr + kk);
                v.x *= smul; v.y *= smul;
                __nv_bfloat162 h, lo2;
                h.x = __float2bfloat16(v.x);
                h.y = __float2bfloat16(v.y);
                lo2.x = __float2bfloat16(v.x - __bfloat162float(h.x));
                lo2.y = __float2bfloat16(v.y - __bfloat162float(h.y));
                *(__nv_bfloat162*)(smem + SM_AH + m * ROWB + kk * 2) = h;
                *(__nv_bfloat162*)(smem + SM_AL + m * ROWB + kk * 2) = lo2;
            }
        }
        __syncthreads();
        // ---- compute ----
#pragma unroll
        for (int ks = 0; ks < 4; ++ks) {
            int kb = ks * 16;
            uint32_t ah[8], al[8], bfr[4];
            uint32_t a_off = (wm * 32 + a_row) * ROWB + (kb + a_kof) * 2;
            ldm_x4(sb + SM_AH + a_off, ah);
            ldm_x4(sb + SM_AH + a_off + 16 * ROWB, ah + 4);
            ldm_x4(sb + SM_AL + a_off, al);
            ldm_x4(sb + SM_AL + a_off + 16 * ROWB, al + 4);
#pragma unroll
            for (int nt = 0; nt < 4; ++nt) {
                uint32_t b_off = (wn * 64 + nt * 16 + b_row) * ROWB + (kb + b_kof) * 2;
                ldm_x4(sb + SM_BH + b_off, bfr);
                mma16816(acc[0][2 * nt], ah, bfr[0], bfr[1]);
                mma16816(acc[0][2 * nt + 1], ah, bfr[2], bfr[3]);
                mma16816(acc[1][2 * nt], ah + 4, bfr[0], bfr[1]);
                mma16816(acc[1][2 * nt + 1], ah + 4, bfr[2], bfr[3]);
                mma16816(acc[0][2 * nt], al, bfr[0], bfr[1]);
                mma16816(acc[0][2 * nt + 1], al, bfr[2], bfr[3]);
                mma16816(acc[1][2 * nt], al + 4, bfr[0], bfr[1]);
                mma16816(acc[1][2 * nt + 1], al + 4, bfr[2], bfr[3]);
                ldm_x4(sb + SM_BL + b_off, bfr);
                mma16816(acc[0][2 * nt], ah, bfr[0], bfr[1]);
                mma16816(acc[0][2 * nt + 1], ah, bfr[2], bfr[3]);
                mma16816(acc[1][2 * nt], ah + 4, bfr[0], bfr[1]);
                mma16816(acc[1][2 * nt + 1], ah + 4, bfr[2], bfr[3]);
            }
        }
        __syncthreads();
    }

    // ---- epilogue: stage C, LN per row ----
    float* Cs = (float*)(smem + 4096);  // [128][132]
    int g = lane >> 2, l2 = (lane & 3) * 2;
#pragma unroll
    for (int mi = 0; mi < 2; ++mi)
#pragma unroll
        for (int ni = 0; ni < 8; ++ni) {
            int row = wm * 32 + mi * 16 + g;
            int col = wn * 64 + ni * 8 + l2;
            *(float2*)(Cs + row * 132 + col) = make_float2(acc[mi][ni][0], acc[mi][ni][1]);
            *(float2*)(Cs + (row + 8) * 132 + col) = make_float2(acc[mi][ni][2], acc[mi][ni][3]);
        }
    __syncthreads();

    float4 b4 = *(const float4*)(shf + 256 + lane * 4);
    float4 g4 = *(const float4*)(shf + 384 + lane * 4);
    float4 be4 = *(const float4*)(shf + 512 + lane * 4);
    for (int r = wid; r < 128; r += 8) {
        int node = m0 + r;
        if (node >= NN) break;
        float4 v = *(const float4*)(Cs + r * 132 + lane * 4);
        v.x += b4.x; v.y += b4.y; v.z += b4.z; v.w += b4.w;
        float s = v.x + v.y + v.z + v.w;
        float q = v.x * v.x + v.y * v.y + v.z * v.z + v.w * v.w;
#pragma unroll
        for (int off = 16; off > 0; off >>= 1) {
            s += __shfl_xor_sync(0xffffffffu, s, off);
            q += __shfl_xor_sync(0xffffffffu, q, off);
        }
        float mu = s * (1.0f / 128.0f);
        float var = q * (1.0f / 128.0f) - mu * mu;
        float rs = rsqrtf(var + 1e-5f);
        float4 xr = *(const float4*)(xin + (size_t)node * 128 + lane * 4);
        float4 o;
        o.x = fmaxf((v.x - mu) * rs * g4.x + be4.x, 0.0f) + xr.x;
        o.y = fmaxf((v.y - mu) * rs * g4.y + be4.y, 0.0f) + xr.y;
        o.z = fmaxf((v.z - mu) * rs * g4.z + be4.z, 0.0f) + xr.z;
        o.w = fmaxf((v.w - mu) * rs * g4.w + be4.w, 0.0f) + xr.w;
        *(float4*)(xout + (size_t)node * 128 + lane * 4) = o;
    }
}

// ---------------- DistMult scoring ----------------
__global__ void k_score(const float* __restrict__ x, const float* __restrict__ qw,
                        const int* __restrict__ src, const int* __restrict__ rel,
                        const int* __restrict__ dst, float* __restrict__ out) {
    int i = (blockIdx.x * blockDim.x + threadIdx.x) >> 5;
    int lane = threadIdx.x & 31;
    if (i >= 32768) return;
    int s = src[i], r = rel[i], d = dst[i];
    float4 a = ((const float4*)(x + (size_t)s * DD))[lane];
    float4 q = ((const float4*)(qw + (size_t)r * DD))[lane];
    float4 b = ((const float4*)(x + (size_t)d * DD))[lane];
    float p = a.x * q.x * b.x + a.y * q.y * b.y + a.z * q.z * b.z + a.w * q.w * b.w;
#pragma unroll
    for (int off = 16; off > 0; off >>= 1) p += __shfl_xor_sync(0xffffffffu, p, off);
    if (lane == 0) out[i] = p;
}

// ---------------- launch ----------------
extern "C" void kernel_launch(void* const* d_in, const int* in_sizes, int n_in,
                              void* d_out, int out_size) {
    const float* x0   = (const float*)d_in[0];
    const int*   ei   = (const int*)d_in[1];
    const int*   etyp = (const int*)d_in[2];
    const float* ew   = (const float*)d_in[3];
    const float* relw = (const float*)d_in[4];
    const float* linw = (const float*)d_in[5];
    const float* linb = (const float*)d_in[6];
    const float* lng  = (const float*)d_in[7];
    const float* lnb  = (const float*)d_in[8];
    const float* qw   = (const float*)d_in[9];
    const int*   src  = (const int*)d_in[10];
    const int*   rel  = (const int*)d_in[11];
    const int*   dst  = (const int*)d_in[12];
    float* out = (float*)d_out;
    const int* es = ei;
    const int* ed = ei + NE;

    cudaFuncSetAttribute(k_linear_mma, cudaFuncAttributeMaxDynamicSharedMemorySize, LIN_SMEM);

    void *pa, *pb, *pf, *pbh, *pbl;
    cudaGetSymbolAddress(&pa, g_xa);
    cudaGetSymbolAddress(&pb, g_xb);
    cudaGetSymbolAddress(&pf, g_feats);
    cudaGetSymbolAddress(&pbh, g_Bhi);
    cudaGetSymbolAddress(&pbl, g_Blo);
    float* XA = (float*)pa;
    float* XB = (float*)pb;
    float* F  = (float*)pf;
    __nv_bfloat16* BH = (__nv_bfloat16*)pbh;
    __nv_bfloat16* BL = (__nv_bfloat16*)pbl;

    k_prepw<<<(4 * NCHUNK * 8192 + 255) / 256, 256>>>(linw);
    k_zero<<<196, 256>>>();
    k_hist<<<1954, 256>>>(ed);
    k_scan<<<1, 1024>>>();
    k_fill<<<1954, 256>>>(ed);
    k_scale_partial<<<NB_SCALE, 512>>>();
    k_scale_final<<<1, 128>>>(NB_SCALE);
    k_scale_write<<<196, 256>>>();

    const float* xi = x0;
    float* xo = XA;
    for (int l = 0; l < 4; l++) {
        k_aggregate<<<6250, 256>>>(xi, x0, relw + (size_t)l * 51 * 128, es, etyp, ew);
        k_linear_mma<<<(NN + 127) / 128, 256, LIN_SMEM>>>(
            F, xi, BH + (size_t)l * NCHUNK * 8192, BL + (size_t)l * NCHUNK * 8192,
            linb + l * 128, lng + l * 128, lnb + l * 128, xo);
        xi = xo;
        xo = (xo == XA) ? XB : XA;
    }
    k_score<<<4096, 256>>>(xi, qw, src, rel, dst, out);
}

// round 4
// speedup vs baseline: 3.2267x; 1.3613x over previous
#include <cuda_runtime.h>
#include <cuda_bf16.h>
#include <math.h>
#include <stdint.h>

#define NN 50000
#define NE 500000
#define DD 128
#define NB_SCALE 98
#define NCHUNK 26
#define NBLK 196   // ceil(50000/256)

// ---------------- device scratch ----------------
__device__ int   g_deg[NN];
__device__ int   g_pos[NN];
__device__ int   g_ptr[NN + 1];
__device__ int   g_bsum[NBLK];
__device__ int   g_boff[NBLK];
__device__ int   g_ssrc[NE];
__device__ int   g_srel[NE];
__device__ float g_sw[NE];
__device__ float g_scale[NN];
__device__ float g_partial[128];
__device__ float g_factor;
__device__ float g_feats[(size_t)NN * 512];
__device__ float g_xa[(size_t)NN * DD];
__device__ float g_xb[(size_t)NN * DD];
// transposed bf16 weight tiles: [4 layers][26 chunks][128 n][64 k]
__device__ __nv_bfloat16 g_Bhi[4 * NCHUNK * 8192];
__device__ __nv_bfloat16 g_Blo[4 * NCHUNK * 8192];

__device__ __forceinline__ uint32_t smem_u32(const void* p) {
    uint32_t a;
    asm("{ .reg .u64 t; cvta.to.shared.u64 t, %1; cvt.u32.u64 %0, t; }" : "=r"(a) : "l"(p));
    return a;
}
__device__ __forceinline__ void ldm_x4(uint32_t addr, uint32_t* r) {
    asm volatile("ldmatrix.sync.aligned.m8n8.x4.shared.b16 {%0,%1,%2,%3}, [%4];"
                 : "=r"(r[0]), "=r"(r[1]), "=r"(r[2]), "=r"(r[3]) : "r"(addr));
}
__device__ __forceinline__ void mma16816(float* c, const uint32_t* a, uint32_t b0, uint32_t b1) {
    asm volatile(
        "mma.sync.aligned.m16n8k16.row.col.f32.bf16.bf16.f32 "
        "{%0,%1,%2,%3}, {%4,%5,%6,%7}, {%8,%9}, {%0,%1,%2,%3};"
        : "+f"(c[0]), "+f"(c[1]), "+f"(c[2]), "+f"(c[3])
        : "r"(a[0]), "r"(a[1]), "r"(a[2]), "r"(a[3]), "r"(b0), "r"(b1));
}
__device__ __forceinline__ void cp16(uint32_t dst, const void* src) {
    asm volatile("cp.async.ca.shared.global [%0], [%1], 16;" :: "r"(dst), "l"(src));
}
#define CP_COMMIT() asm volatile("cp.async.commit_group;" ::: "memory")
#define CP_WAIT0()  asm volatile("cp.async.wait_group 0;" ::: "memory")

// ---------------- CSR build ----------------
__global__ void k_zero() {
    int i = blockIdx.x * blockDim.x + threadIdx.x;
    if (i < NN) { g_deg[i] = 0; g_pos[i] = 0; }
}
__global__ void k_hist(const int* __restrict__ ed) {
    int e = blockIdx.x * blockDim.x + threadIdx.x;
    if (e < NE) atomicAdd(&g_deg[ed[e]], 1);
}
// scan A: per-block inclusive scan -> g_ptr (temp), block sums -> g_bsum
__global__ void k_scanA() {
    int b = blockIdx.x, t = threadIdx.x, i = b * 256 + t;
    int v = (i < NN) ? g_deg[i] : 0;
    int lane = t & 31, w = t >> 5;
    int x = v;
#pragma unroll
    for (int off = 1; off < 32; off <<= 1) {
        int y = __shfl_up_sync(0xffffffffu, x, off);
        if (lane >= off) x += y;
    }
    __shared__ int ws[8];
    if (lane == 31) ws[w] = x;
    __syncthreads();
    int add = 0;
#pragma unroll
    for (int j = 0; j < 8; j++) if (j < w) add += ws[j];
    x += add;
    if (i < NN) g_ptr[i] = x;
    if (t == 255) g_bsum[b] = x;
}
// scan B: exclusive scan of 196 block sums
__global__ void k_scanB() {
    int t = threadIdx.x;
    int v = (t < NBLK) ? g_bsum[t] : 0;
    int lane = t & 31, w = t >> 5;
    int x = v;
#pragma unroll
    for (int off = 1; off < 32; off <<= 1) {
        int y = __shfl_up_sync(0xffffffffu, x, off);
        if (lane >= off) x += y;
    }
    __shared__ int ws[8];
    if (lane == 31) ws[w] = x;
    __syncthreads();
    int add = 0;
#pragma unroll
    for (int j = 0; j < 8; j++) if (j < w) add += ws[j];
    x += add;
    if (t < NBLK) g_boff[t] = x - v;
    if (t == NBLK - 1) g_ptr[NN] = x;
}
// scan C: finalize exclusive global scan
__global__ void k_scanC() {
    int b = blockIdx.x, t = threadIdx.x, i = b * 256 + t;
    if (i < NN) g_ptr[i] = g_ptr[i] - g_deg[i] + g_boff[b];
}
// fill slot records (src, rel, weight) grouped by dst
__global__ void k_fill(const int* __restrict__ es, const int* __restrict__ ed,
                       const int* __restrict__ et, const float* __restrict__ ew) {
    int e = blockIdx.x * blockDim.x + threadIdx.x;
    if (e < NE) {
        int d = ed[e];
        int p = atomicAdd(&g_pos[d], 1);
        int slot = g_ptr[d] + p;
        g_ssrc[slot] = es[e];
        g_srel[slot] = et[e];
        g_sw[slot] = ew[e];
    }
}
__global__ void k_scale_partial() {
    __shared__ float sh[512];
    int t = threadIdx.x;
    int i = blockIdx.x * 512 + t;
    float v = (i < NN) ? logf((float)g_deg[i] + 1.0f) : 0.0f;
    sh[t] = v;
    __syncthreads();
    for (int off = 256; off > 0; off >>= 1) {
        if (t < off) sh[t] += sh[t + off];
        __syncthreads();
    }
    if (t == 0) g_partial[blockIdx.x] = sh[0];
}
__global__ void k_scale_final(int nb) {
    __shared__ float sh[128];
    int t = threadIdx.x;
    sh[t] = (t < nb) ? g_partial[t] : 0.0f;
    __syncthreads();
    for (int off = 64; off > 0; off >>= 1) {
        if (t < off) sh[t] += sh[t + off];
        __syncthreads();
    }
    if (t == 0) g_factor = (float)NN / sh[0];
}
__global__ void k_scale_write() {
    int i = blockIdx.x * blockDim.x + threadIdx.x;
    if (i < NN) g_scale[i] = logf((float)g_deg[i] + 1.0f) * g_factor;
}

// ---------------- weight prep: smem transpose + bf16 split ----------------
// grid = 4*26 blocks; block handles one [64 k][128 n] fp32 tile -> [128 n][64 k] bf16 hi/lo
__global__ void k_prepw(const float* __restrict__ linw) {
    __shared__ float ts[64][129];
    int tile = blockIdx.x;
    int l = tile / NCHUNK, kt = tile - l * NCHUNK;
    const float* src = linw + ((size_t)l * 1664 + kt * 64) * 128;
    for (int i = threadIdx.x; i < 8192; i += 256) {
        int k = i >> 7, n = i & 127;
        ts[k][n] = src[i];
    }
    __syncthreads();
    __nv_bfloat16* bh = g_Bhi + (size_t)tile * 8192;
    __nv_bfloat16* bl = g_Blo + (size_t)tile * 8192;
    for (int i = threadIdx.x; i < 8192; i += 256) {
        int n = i >> 6, kk = i & 63;
        float w = ts[kk][n];
        __nv_bfloat16 h = __float2bfloat16(w);
        bh[i] = h;
        bl[i] = __float2bfloat16(w - __bfloat162float(h));
    }
}

// ---------------- per-layer aggregation: warp/node, slot records, 1-deep prefetch ----------------
__global__ void k_aggregate(const float* __restrict__ x, const float* __restrict__ x0,
                            const float* __restrict__ relw) {
    int gw = (blockIdx.x * blockDim.x + threadIdx.x) >> 5;
    int lane = threadIdx.x & 31;
    if (gw >= NN) return;
    int n = gw;
    float4 b = ((const float4*)(x0 + (size_t)n * DD))[lane];
    float4 sum = b, mx = b, mn = b;
    float4 ssq = make_float4(b.x * b.x, b.y * b.y, b.z * b.z, b.w * b.w);
    int p0 = g_ptr[n], p1 = g_ptr[n + 1];
    float4 xv, rv;
    float w = 0.f;
    if (p0 < p1) {
        int s = g_ssrc[p0], r = g_srel[p0];
        w = g_sw[p0];
        xv = ((const float4*)(x + (size_t)s * DD))[lane];
        rv = ((const float4*)(relw + (size_t)r * DD))[lane];
    }
    for (int p = p0; p < p1; ++p) {
        float4 cx = xv, cr = rv;
        float cw = w;
        if (p + 1 < p1) {
            int s2 = g_ssrc[p + 1], r2 = g_srel[p + 1];
            w = g_sw[p + 1];
            xv = ((const float4*)(x + (size_t)s2 * DD))[lane];
            rv = ((const float4*)(relw + (size_t)r2 * DD))[lane];
        }
        float4 m = make_float4(cx.x * cr.x * cw, cx.y * cr.y * cw, cx.z * cr.z * cw, cx.w * cr.w * cw);
        sum.x += m.x; sum.y += m.y; sum.z += m.z; sum.w += m.w;
        ssq.x += m.x * m.x; ssq.y += m.y * m.y; ssq.z += m.z * m.z; ssq.w += m.w * m.w;
        mx.x = fmaxf(mx.x, m.x); mx.y = fmaxf(mx.y, m.y); mx.z = fmaxf(mx.z, m.z); mx.w = fmaxf(mx.w, m.w);
        mn.x = fminf(mn.x, m.x); mn.y = fminf(mn.y, m.y); mn.z = fminf(mn.z, m.z); mn.w = fminf(mn.w, m.w);
    }
    float invd = 1.0f / (float)(p1 - p0 + 1);
    float4 mean = make_float4(sum.x * invd, sum.y * invd, sum.z * invd, sum.w * invd);
    float4 sq = make_float4(ssq.x * invd, ssq.y * invd, ssq.z * invd, ssq.w * invd);
    float4 sd;
    sd.x = sqrtf(fmaxf(sq.x - mean.x * mean.x, 1e-6f));
    sd.y = sqrtf(fmaxf(sq.y - mean.y * mean.y, 1e-6f));
    sd.z = sqrtf(fmaxf(sq.z - mean.z * mean.z, 1e-6f));
    sd.w = sqrtf(fmaxf(sq.w - mean.w * mean.w, 1e-6f));
    float4* out = (float4*)(g_feats + (size_t)n * 512);
    out[0 * 32 + lane] = mean;
    out[1 * 32 + lane] = mx;
    out[2 * 32 + lane] = mn;
    out[3 * 32 + lane] = sd;
}

// ---------------- pipelined mma.sync fused linear + LN + ReLU + residual ----------------
// CTA 128x128, warp grid 4(M)x2(N). Double-buffered smem; cp.async B; reg-staged A.
#define SM_HDR 4096
#define BUFSZ 73728
#define OF_AH 0
#define OF_AL 18432
#define OF_BH 36864
#define OF_BL 55296
#define ROWB 144
#define LIN_SMEM (SM_HDR + 2 * BUFSZ)   // 151552

__global__ void __launch_bounds__(256, 1) k_linear_mma(
    const float* __restrict__ feats, const float* __restrict__ xin,
    const __nv_bfloat16* __restrict__ Bh, const __nv_bfloat16* __restrict__ Bl,
    const float* __restrict__ bias, const float* __restrict__ gam,
    const float* __restrict__ bet, float* __restrict__ xout) {
    extern __shared__ char smem[];
    uint32_t sb = smem_u32(smem);
    float* shf = (float*)smem;
    int t = threadIdx.x, wid = t >> 5, lane = t & 31;
    int m0 = blockIdx.x * 128;
    int wm = wid >> 1, wn = wid & 1;

    if (t < 128) {
        int node = min(m0 + t, NN - 1);
        float s1 = g_scale[node];
        shf[t] = s1;
        shf[128 + t] = 1.0f / fmaxf(s1, 1e-2f);
        shf[256 + t] = bias[t];
        shf[384 + t] = gam[t];
        shf[512 + t] = bet[t];
    }
    __syncthreads();

    float acc[2][8][4];
#pragma unroll
    for (int i = 0; i < 2; i++)
#pragma unroll
        for (int j = 0; j < 8; j++)
#pragma unroll
            for (int q = 0; q < 4; q++) acc[i][j][q] = 0.0f;

    // ldmatrix lane addressing
    int aidx = lane & 7, agrp = lane >> 3;
    int a_row = aidx + ((agrp & 1) ? 8 : 0);
    int a_kof = (agrp & 2) ? 8 : 0;
    int b_row = aidx + ((agrp & 2) ? 8 : 0);
    int b_kof = (agrp & 1) ? 8 : 0;

    float4 v[8];

    // ---- helpers as macros (kt known at each site) ----
#define BUFBASE(kt) (SM_HDR + ((kt) & 1) * BUFSZ)

#define ISSUE_B(kt) do { \
        const char* _bh = (const char*)(Bh + (size_t)(kt) * 8192); \
        const char* _bl = (const char*)(Bl + (size_t)(kt) * 8192); \
        uint32_t _bb = sb + BUFBASE(kt); \
        _Pragma("unroll") \
        for (int _q = 0; _q < 4; ++_q) { \
            int _i = t + _q * 256; \
            int _n = _i >> 3, _c = _i & 7; \
            cp16(_bb + OF_BH + _n * ROWB + _c * 16, _bh + _i * 16); \
            cp16(_bb + OF_BL + _n * ROWB + _c * 16, _bl + _i * 16); \
        } \
    } while (0)

#define LOAD_A(kt) do { \
        int _c0 = (kt) * 64; \
        bool _isx = (_c0 >= 1536); \
        int _f = (_c0 >> 7) & 3, _ko = _c0 & 127; \
        _Pragma("unroll") \
        for (int _it = 0; _it < 8; ++_it) { \
            int _e = t + _it * 256; \
            int _m = _e >> 4, _kk = (_e & 15) * 4; \
            int _node = min(m0 + _m, NN - 1); \
            const float* _sr = _isx ? (xin + (size_t)_node * 128 + (_c0 - 1536) + _kk) \
                                    : (feats + (size_t)_node * 512 + _f * 128 + _ko + _kk); \
            v[_it] = *(const float4*)_sr; \
        } \
    } while (0)

#define STORE_A(kt) do { \
        int _c0 = (kt) * 64; \
        int _j = _c0 >> 9; \
        bool _isx = (_c0 >= 1536); \
        char* _ab = smem + BUFBASE(kt); \
        _Pragma("unroll") \
        for (int _it = 0; _it < 8; ++_it) { \
            int _e = t + _it * 256; \
            int _m = _e >> 4, _kk = (_e & 15) * 4; \
            float _sm = (_isx || _j == 0) ? 1.0f : ((_j == 1) ? shf[_m] : shf[128 + _m]); \
            float4 _w = v[_it]; \
            _w.x *= _sm; _w.y *= _sm; _w.z *= _sm; _w.w *= _sm; \
            __nv_bfloat162 _h0, _h1, _l0, _l1; \
            _h0.x = __float2bfloat16(_w.x); _h0.y = __float2bfloat16(_w.y); \
            _h1.x = __float2bfloat16(_w.z); _h1.y = __float2bfloat16(_w.w); \
            _l0.x = __float2bfloat16(_w.x - __bfloat162float(_h0.x)); \
            _l0.y = __float2bfloat16(_w.y - __bfloat162float(_h0.y)); \
            _l1.x = __float2bfloat16(_w.z - __bfloat162float(_h1.x)); \
            _l1.y = __float2bfloat16(_w.w - __bfloat162float(_h1.y)); \
            char* _pa = _ab + OF_AH + _m * ROWB + _kk * 2; \
            char* _pl = _ab + OF_AL + _m * ROWB + _kk * 2; \
            *(__nv_bfloat162*)_pa = _h0; *(__nv_bfloat162*)(_pa + 4) = _h1; \
            *(__nv_bfloat162*)_pl = _l0; *(__nv_bfloat162*)(_pl + 4) = _l1; \
        } \
    } while (0)

    // prologue: chunk 0
    LOAD_A(0);
    ISSUE_B(0);
    CP_COMMIT();
    STORE_A(0);
    CP_WAIT0();
    __syncthreads();

    for (int kt = 0; kt < NCHUNK; ++kt) {
        if (kt + 1 < NCHUNK) {
            LOAD_A(kt + 1);
            ISSUE_B(kt + 1);
        }
        CP_COMMIT();
        uint32_t tb = sb + BUFBASE(kt);
#pragma unroll
        for (int ks = 0; ks < 4; ++ks) {
            int kb = ks * 16;
            uint32_t ah[8], al[8], bfr[4];
            uint32_t a_off = (wm * 32 + a_row) * ROWB + (kb + a_kof) * 2;
            ldm_x4(tb + OF_AH + a_off, ah);
            ldm_x4(tb + OF_AH + a_off + 16 * ROWB, ah + 4);
            ldm_x4(tb + OF_AL + a_off, al);
            ldm_x4(tb + OF_AL + a_off + 16 * ROWB, al + 4);
#pragma unroll
            for (int nt = 0; nt < 4; ++nt) {
                uint32_t b_off = (wn * 64 + nt * 16 + b_row) * ROWB + (kb + b_kof) * 2;
                ldm_x4(tb + OF_BH + b_off, bfr);
                mma16816(acc[0][2 * nt], ah, bfr[0], bfr[1]);
                mma16816(acc[0][2 * nt + 1], ah, bfr[2], bfr[3]);
                mma16816(acc[1][2 * nt], ah + 4, bfr[0], bfr[1]);
                mma16816(acc[1][2 * nt + 1], ah + 4, bfr[2], bfr[3]);
                mma16816(acc[0][2 * nt], al, bfr[0], bfr[1]);
                mma16816(acc[0][2 * nt + 1], al, bfr[2], bfr[3]);
                mma16816(acc[1][2 * nt], al + 4, bfr[0], bfr[1]);
                mma16816(acc[1][2 * nt + 1], al + 4, bfr[2], bfr[3]);
                ldm_x4(tb + OF_BL + b_off, bfr);
                mma16816(acc[0][2 * nt], ah, bfr[0], bfr[1]);
                mma16816(acc[0][2 * nt + 1], ah, bfr[2], bfr[3]);
                mma16816(acc[1][2 * nt], ah + 4, bfr[0], bfr[1]);
                mma16816(acc[1][2 * nt + 1], ah + 4, bfr[2], bfr[3]);
            }
        }
        if (kt + 1 < NCHUNK) STORE_A(kt + 1);
        CP_WAIT0();
        __syncthreads();
    }

    // ---- epilogue: stage C, LN per row ----
    float* Cs = (float*)(smem + SM_HDR);  // [128][132]
    int g = lane >> 2, l2 = (lane & 3) * 2;
#pragma unroll
    for (int mi = 0; mi < 2; ++mi)
#pragma unroll
        for (int ni = 0; ni < 8; ++ni) {
            int row = wm * 32 + mi * 16 + g;
            int col = wn * 64 + ni * 8 + l2;
            *(float2*)(Cs + row * 132 + col) = make_float2(acc[mi][ni][0], acc[mi][ni][1]);
            *(float2*)(Cs + (row + 8) * 132 + col) = make_float2(acc[mi][ni][2], acc[mi][ni][3]);
        }
    __syncthreads();

    float4 b4 = *(const float4*)(shf + 256 + lane * 4);
    float4 g4 = *(const float4*)(shf + 384 + lane * 4);
    float4 be4 = *(const float4*)(shf + 512 + lane * 4);
    for (int r = wid; r < 128; r += 8) {
        int node = m0 + r;
        if (node >= NN) break;
        float4 vv = *(const float4*)(Cs + r * 132 + lane * 4);
        vv.x += b4.x; vv.y += b4.y; vv.z += b4.z; vv.w += b4.w;
        float s = vv.x + vv.y + vv.z + vv.w;
        float q = vv.x * vv.x + vv.y * vv.y + vv.z * vv.z + vv.w * vv.w;
#pragma unroll
        for (int off = 16; off > 0; off >>= 1) {
            s += __shfl_xor_sync(0xffffffffu, s, off);
            q += __shfl_xor_sync(0xffffffffu, q, off);
        }
        float mu = s * (1.0f / 128.0f);
        float var = q * (1.0f / 128.0f) - mu * mu;
        float rs = rsqrtf(var + 1e-5f);
        float4 xr = *(const float4*)(xin + (size_t)node * 128 + lane * 4);
        float4 o;
        o.x = fmaxf((vv.x - mu) * rs * g4.x + be4.x, 0.0f) + xr.x;
        o.y = fmaxf((vv.y - mu) * rs * g4.y + be4.y, 0.0f) + xr.y;
        o.z = fmaxf((vv.z - mu) * rs * g4.z + be4.z, 0.0f) + xr.z;
        o.w = fmaxf((vv.w - mu) * rs * g4.w + be4.w, 0.0f) + xr.w;
        *(float4*)(xout + (size_t)node * 128 + lane * 4) = o;
    }
}

// ---------------- DistMult scoring ----------------
__global__ void k_score(const float* __restrict__ x, const float* __restrict__ qw,
                        const int* __restrict__ src, const int* __restrict__ rel,
                        const int* __restrict__ dst, float* __restrict__ out) {
    int i = (blockIdx.x * blockDim.x + threadIdx.x) >> 5;
    int lane = threadIdx.x & 31;
    if (i >= 32768) return;
    int s = src[i], r = rel[i], d = dst[i];
    float4 a = ((const float4*)(x + (size_t)s * DD))[lane];
    float4 q = ((const float4*)(qw + (size_t)r * DD))[lane];
    float4 b = ((const float4*)(x + (size_t)d * DD))[lane];
    float p = a.x * q.x * b.x + a.y * q.y * b.y + a.z * q.z * b.z + a.w * q.w * b.w;
#pragma unroll
    for (int off = 16; off > 0; off >>= 1) p += __shfl_xor_sync(0xffffffffu, p, off);
    if (lane == 0) out[i] = p;
}

// ---------------- launch ----------------
extern "C" void kernel_launch(void* const* d_in, const int* in_sizes, int n_in,
                              void* d_out, int out_size) {
    const float* x0   = (const float*)d_in[0];
    const int*   ei   = (const int*)d_in[1];
    const int*   etyp = (const int*)d_in[2];
    const float* ew   = (const float*)d_in[3];
    const float* relw = (const float*)d_in[4];
    const float* linw = (const float*)d_in[5];
    const float* linb = (const float*)d_in[6];
    const float* lng  = (const float*)d_in[7];
    const float* lnb  = (const float*)d_in[8];
    const float* qw   = (const float*)d_in[9];
    const int*   src  = (const int*)d_in[10];
    const int*   rel  = (const int*)d_in[11];
    const int*   dst  = (const int*)d_in[12];
    float* out = (float*)d_out;
    const int* es = ei;
    const int* ed = ei + NE;

    cudaFuncSetAttribute(k_linear_mma, cudaFuncAttributeMaxDynamicSharedMemorySize, LIN_SMEM);

    void *pa, *pb, *pf, *pbh, *pbl;
    cudaGetSymbolAddress(&pa, g_xa);
    cudaGetSymbolAddress(&pb, g_xb);
    cudaGetSymbolAddress(&pf, g_feats);
    cudaGetSymbolAddress(&pbh, g_Bhi);
    cudaGetSymbolAddress(&pbl, g_Blo);
    float* XA = (float*)pa;
    float* XB = (float*)pb;
    float* F  = (float*)pf;
    __nv_bfloat16* BH = (__nv_bfloat16*)pbh;
    __nv_bfloat16* BL = (__nv_bfloat16*)pbl;

    k_prepw<<<4 * NCHUNK, 256>>>(linw);
    k_zero<<<196, 256>>>();
    k_hist<<<1954, 256>>>(ed);
    k_scanA<<<NBLK, 256>>>();
    k_scanB<<<1, 256>>>();
    k_scanC<<<NBLK, 256>>>();
    k_fill<<<1954, 256>>>(es, ed, etyp, ew);
    k_scale_partial<<<NB_SCALE, 512>>>();
    k_scale_final<<<1, 128>>>(NB_SCALE);
    k_scale_write<<<196, 256>>>();

    const float* xi = x0;
    float* xo = XA;
    for (int l = 0; l < 4; l++) {
        k_aggregate<<<6250, 256>>>(xi, x0, relw + (size_t)l * 51 * 128);
        k_linear_mma<<<(NN + 127) / 128, 256, LIN_SMEM>>>(
            F, xi, BH + (size_t)l * NCHUNK * 8192, BL + (size_t)l * NCHUNK * 8192,
            linb + l * 128, lng + l * 128, lnb + l * 128, xo);
        xi = xo;
        xo = (xo == XA) ? XB : XA;
    }
    k_score<<<4096, 256>>>(xi, qw, src, rel, dst, out);
}